// round 1
// baseline (speedup 1.0000x reference)
#include <cuda_runtime.h>
#include <cuda_bf16.h>
#include <stdint.h>

// Problem constants
static constexpr int Bn = 4, Gn = 6, Hn = 8, Sn = 1024, DKn = 64, DMn = 512;
static constexpr int BG   = Bn * Gn;        // 24
static constexpr int BGH  = BG * Hn;        // 192
static constexpr int MROWS = BG * Sn;       // 24576
static constexpr int P_ELEMS = 201326592;   // 192*1024*1024
static constexpr int Y_ELEMS = BG * DMn;    // 12288

// Scratch (__device__ globals: allocation-free)
__device__ __align__(16) __nv_bfloat16 g_q[(size_t)MROWS * DMn];
__device__ __align__(16) __nv_bfloat16 g_k[(size_t)MROWS * DMn];
__device__ __align__(16) float g_wbar[BGH * Sn];

__device__ __forceinline__ void mma16816(float c[4], const uint32_t a[4], const uint32_t b[2]) {
    asm volatile(
        "mma.sync.aligned.m16n8k16.row.col.f32.bf16.bf16.f32 "
        "{%0,%1,%2,%3},{%4,%5,%6,%7},{%8,%9},{%0,%1,%2,%3};\n"
        : "+f"(c[0]), "+f"(c[1]), "+f"(c[2]), "+f"(c[3])
        : "r"(a[0]), "r"(a[1]), "r"(a[2]), "r"(a[3]), "r"(b[0]), "r"(b[1]));
}

// ---------------------------------------------------------------------------
// Zero wbar (192*1024 floats)
__global__ void zero_wbar_kernel() {
    int i = blockIdx.x * 1024 + threadIdx.x * 4;
    *(float4*)&g_wbar[i] = make_float4(0.f, 0.f, 0.f, 0.f);
}

// ---------------------------------------------------------------------------
// Projection: y = x @ W^T + b, output bf16 in (bg, h, s, d) layout.
// Grid: (192 m-tiles, 4 n-tiles, 2 {q,k}), 256 threads.
__global__ __launch_bounds__(256) void proj_kernel(
    const float* __restrict__ xq, const float* __restrict__ xk,
    const float* __restrict__ Wq, const float* __restrict__ bq,
    const float* __restrict__ Wk, const float* __restrict__ bk)
{
    const int which = blockIdx.z;
    const float* __restrict__ X  = which ? xk : xq;
    const float* __restrict__ W  = which ? Wk : Wq;
    const float* __restrict__ Bi = which ? bk : bq;
    __nv_bfloat16* O = which ? g_k : g_q;

    const int m0 = blockIdx.x * 128;
    const int n0 = blockIdx.y * 128;
    const int tid = threadIdx.x;
    const int w = tid >> 5, lane = tid & 31;
    const int gq = lane >> 2, tq = lane & 3;
    const int wm = w >> 1, wn = w & 1;   // 4x2 warp grid -> warp tile 32(m) x 64(n)

    __shared__ __nv_bfloat16 As[128 * 40];
    __shared__ __nv_bfloat16 Bs[128 * 40];

    float acc[2][8][4];
#pragma unroll
    for (int mi = 0; mi < 2; mi++)
#pragma unroll
        for (int ni = 0; ni < 8; ni++)
#pragma unroll
            for (int x = 0; x < 4; x++) acc[mi][ni][x] = 0.f;

    float4 ra[4], rb[4];
#pragma unroll
    for (int j = 0; j < 4; j++) {
        int i = tid + 256 * j;
        int r = i >> 3, c4 = (i & 7) * 4;
        ra[j] = *(const float4*)&X[(size_t)(m0 + r) * DMn + c4];
        rb[j] = *(const float4*)&W[(size_t)(n0 + r) * DMn + c4];
    }

    for (int kc = 0; kc < 16; kc++) {
        __syncthreads();
#pragma unroll
        for (int j = 0; j < 4; j++) {
            int i = tid + 256 * j;
            int r = i >> 3, c4 = (i & 7) * 4;
            __nv_bfloat162 lo = __floats2bfloat162_rn(ra[j].x, ra[j].y);
            __nv_bfloat162 hi = __floats2bfloat162_rn(ra[j].z, ra[j].w);
            *(__nv_bfloat162*)&As[r * 40 + c4]     = lo;
            *(__nv_bfloat162*)&As[r * 40 + c4 + 2] = hi;
            lo = __floats2bfloat162_rn(rb[j].x, rb[j].y);
            hi = __floats2bfloat162_rn(rb[j].z, rb[j].w);
            *(__nv_bfloat162*)&Bs[r * 40 + c4]     = lo;
            *(__nv_bfloat162*)&Bs[r * 40 + c4 + 2] = hi;
        }
        __syncthreads();
        if (kc < 15) {
            int kk = (kc + 1) * 32;
#pragma unroll
            for (int j = 0; j < 4; j++) {
                int i = tid + 256 * j;
                int r = i >> 3, c4 = (i & 7) * 4;
                ra[j] = *(const float4*)&X[(size_t)(m0 + r) * DMn + kk + c4];
                rb[j] = *(const float4*)&W[(size_t)(n0 + r) * DMn + kk + c4];
            }
        }
#pragma unroll
        for (int ks = 0; ks < 32; ks += 16) {
            uint32_t af[2][4];
#pragma unroll
            for (int mi = 0; mi < 2; mi++) {
                int ar = wm * 32 + mi * 16;
                af[mi][0] = *(const uint32_t*)&As[(ar + gq) * 40 + ks + 2 * tq];
                af[mi][1] = *(const uint32_t*)&As[(ar + gq + 8) * 40 + ks + 2 * tq];
                af[mi][2] = *(const uint32_t*)&As[(ar + gq) * 40 + ks + 2 * tq + 8];
                af[mi][3] = *(const uint32_t*)&As[(ar + gq + 8) * 40 + ks + 2 * tq + 8];
            }
#pragma unroll
            for (int ni = 0; ni < 8; ni++) {
                int br = wn * 64 + ni * 8 + gq;
                uint32_t bf[2];
                bf[0] = *(const uint32_t*)&Bs[br * 40 + ks + 2 * tq];
                bf[1] = *(const uint32_t*)&Bs[br * 40 + ks + 2 * tq + 8];
#pragma unroll
                for (int mi = 0; mi < 2; mi++) mma16816(acc[mi][ni], af[mi], bf);
            }
        }
    }

    // Epilogue: +bias, convert bf16, write to (bg,h,s,d) layout
#pragma unroll
    for (int ni = 0; ni < 8; ni++) {
        int cc = n0 + wn * 64 + ni * 8 + 2 * tq;
        float b0v = Bi[cc], b1v = Bi[cc + 1];
        int h = cc >> 6, d = cc & 63;
#pragma unroll
        for (int mi = 0; mi < 2; mi++) {
            int rbase = m0 + wm * 32 + mi * 16 + gq;
#pragma unroll
            for (int rr = 0; rr < 2; rr++) {
                int r = rbase + rr * 8;
                int bg = r >> 10, s = r & 1023;
                size_t off = ((size_t)(bg * Hn + h) * Sn + s) * DKn + d;
                float v0 = acc[mi][ni][rr * 2 + 0] + b0v;
                float v1 = acc[mi][ni][rr * 2 + 1] + b1v;
                *(__nv_bfloat162*)&O[off] = __floats2bfloat162_rn(v0, v1);
            }
        }
    }
}

// ---------------------------------------------------------------------------
// Attention: per CTA = (32 q-rows) x (full 1024 k) of one (b,g,h).
// Single pass: bf16 MMA scores -> exp into smem -> rowsum -> normalized write
// + column-sum atomics into g_wbar.
static constexpr int ESTR = 1028;  // padded fp32 row stride for e-tile
static constexpr int ATTN_SMEM = 32 * ESTR * 4      // e tile      131584
                               + 32 * 72 * 2        // q tile        4608
                               + 128 * 72 * 2       // k chunk      18432
                               + 32 * 4;            // rowsum         128

__global__ __launch_bounds__(256) void attn_kernel(float* __restrict__ out, int p_base, int write_p)
{
    extern __shared__ char smbuf[];
    float*        es  = (float*)smbuf;
    __nv_bfloat16* qs  = (__nv_bfloat16*)(smbuf + 32 * ESTR * 4);
    __nv_bfloat16* ksm = (__nv_bfloat16*)(smbuf + 32 * ESTR * 4 + 32 * 72 * 2);
    float*        rsum = (float*)(smbuf + 32 * ESTR * 4 + 32 * 72 * 2 + 128 * 72 * 2);

    const int qt = blockIdx.x, bgh = blockIdx.y;
    const int tid = threadIdx.x;
    const int w = tid >> 5, lane = tid & 31;
    const int gq = lane >> 2, tq = lane & 3;
    const int wm = w & 1, wn = w >> 1;   // 2(m) x 4(n) warp grid over 32 x 128

    const __nv_bfloat16* qbase = g_q + (size_t)bgh * (Sn * DKn) + (size_t)qt * 32 * DKn;
    const __nv_bfloat16* kbase = g_k + (size_t)bgh * (Sn * DKn);

    // load q tile (32x64 bf16) into smem, padded stride 72
    {
        int r = tid >> 3, part = tid & 7;
        *(uint4*)&qs[r * 72 + part * 8] = *(const uint4*)&qbase[r * DKn + part * 8];
    }
    if (tid < 32) rsum[tid] = 0.f;

    float rs0 = 0.f, rs1 = 0.f;

    uint4 pre[4];
#pragma unroll
    for (int j = 0; j < 4; j++) {
        int i = tid + 256 * j;
        int r = i >> 3, part = i & 7;
        pre[j] = *(const uint4*)&kbase[(size_t)r * DKn + part * 8];
    }

    const float SCL = 1.0f / 1200.0f;  // 1/(sqrt(64)*150)

    for (int c = 0; c < 8; c++) {
        __syncthreads();
#pragma unroll
        for (int j = 0; j < 4; j++) {
            int i = tid + 256 * j;
            int r = i >> 3, part = i & 7;
            *(uint4*)&ksm[r * 72 + part * 8] = pre[j];
        }
        __syncthreads();
        if (c < 7) {
#pragma unroll
            for (int j = 0; j < 4; j++) {
                int i = tid + 256 * j;
                int r = i >> 3, part = i & 7;
                pre[j] = *(const uint4*)&kbase[(size_t)((c + 1) * 128 + r) * DKn + part * 8];
            }
        }

        float acc[4][4];
#pragma unroll
        for (int ni = 0; ni < 4; ni++)
#pragma unroll
            for (int x = 0; x < 4; x++) acc[ni][x] = 0.f;

#pragma unroll
        for (int ks = 0; ks < 64; ks += 16) {
            uint32_t af[4];
            int ar = wm * 16;
            af[0] = *(const uint32_t*)&qs[(ar + gq) * 72 + ks + 2 * tq];
            af[1] = *(const uint32_t*)&qs[(ar + gq + 8) * 72 + ks + 2 * tq];
            af[2] = *(const uint32_t*)&qs[(ar + gq) * 72 + ks + 2 * tq + 8];
            af[3] = *(const uint32_t*)&qs[(ar + gq + 8) * 72 + ks + 2 * tq + 8];
#pragma unroll
            for (int ni = 0; ni < 4; ni++) {
                int br = wn * 32 + ni * 8 + gq;
                uint32_t bf[2];
                bf[0] = *(const uint32_t*)&ksm[br * 72 + ks + 2 * tq];
                bf[1] = *(const uint32_t*)&ksm[br * 72 + ks + 2 * tq + 8];
                mma16816(acc[ni], af, bf);
            }
        }

        int r0 = wm * 16 + gq;
#pragma unroll
        for (int ni = 0; ni < 4; ni++) {
            int cc = c * 128 + wn * 32 + ni * 8 + 2 * tq;
            float e00 = __expf(acc[ni][0] * SCL);
            float e01 = __expf(acc[ni][1] * SCL);
            float e10 = __expf(acc[ni][2] * SCL);
            float e11 = __expf(acc[ni][3] * SCL);
            *(float2*)&es[r0 * ESTR + cc]       = make_float2(e00, e01);
            *(float2*)&es[(r0 + 8) * ESTR + cc] = make_float2(e10, e11);
            rs0 += e00 + e01;
            rs1 += e10 + e11;
        }
    }

    // reduce row partials within lane quads, then shared atomics
    rs0 += __shfl_xor_sync(0xffffffffu, rs0, 1);
    rs0 += __shfl_xor_sync(0xffffffffu, rs0, 2);
    rs1 += __shfl_xor_sync(0xffffffffu, rs1, 1);
    rs1 += __shfl_xor_sync(0xffffffffu, rs1, 2);
    if (tq == 0) {
        atomicAdd(&rsum[wm * 16 + gq], rs0);
        atomicAdd(&rsum[wm * 16 + 8 + gq], rs1);
    }
    __syncthreads();
    if (tid < 32) rsum[tid] = 1.0f / rsum[tid];   // invert once
    __syncthreads();

    // normalize + write p + accumulate column sums (thread owns cols tid*4..+3)
    float cs0 = 0.f, cs1 = 0.f, cs2 = 0.f, cs3 = 0.f;
    float* pout = out + p_base + (size_t)bgh * ((size_t)Sn * Sn) + (size_t)(qt * 32) * Sn;
#pragma unroll 4
    for (int r = 0; r < 32; r++) {
        float inv = rsum[r];
        float4 v = *(const float4*)&es[r * ESTR + tid * 4];
        v.x *= inv; v.y *= inv; v.z *= inv; v.w *= inv;
        cs0 += v.x; cs1 += v.y; cs2 += v.z; cs3 += v.w;
        if (write_p) *(float4*)&pout[(size_t)r * Sn + tid * 4] = v;
    }
    atomicAdd(&g_wbar[bgh * Sn + tid * 4 + 0], cs0);
    atomicAdd(&g_wbar[bgh * Sn + tid * 4 + 1], cs1);
    atomicAdd(&g_wbar[bgh * Sn + tid * 4 + 2], cs2);
    atomicAdd(&g_wbar[bgh * Sn + tid * 4 + 3], cs3);
}

// ---------------------------------------------------------------------------
// Finalize: t = (wbar/1024) @ Xv ; out_hd = t_h . Wv[h*64+d] + bv ;
// f[d*8+h] = out_hd ; y = f @ Wo^T + bo.  One CTA per (b,g), 512 threads.
static constexpr int F_SMEM = 8 * 1024 * 4 + 8 * 512 * 4 + 512 * 4;  // 51200

__global__ __launch_bounds__(512) void finalize_kernel(
    const float* __restrict__ value, const float* __restrict__ Wv, const float* __restrict__ bv,
    const float* __restrict__ Wo, const float* __restrict__ bo,
    float* __restrict__ out, int write_y)
{
    extern __shared__ float sf[];
    float* wb = sf;               // [8][1024]
    float* ts = sf + 8 * 1024;    // [8][512]
    float* fs = ts + 8 * 512;     // [512]
    const int bg = blockIdx.x, tid = threadIdx.x;
    const float invS = 1.0f / 1024.0f;

#pragma unroll
    for (int j = 0; j < 16; j++) {
        int i = tid + 512 * j;
        wb[i] = g_wbar[bg * 8192 + i] * invS;
    }
    __syncthreads();

    {
        float a0=0,a1=0,a2=0,a3=0,a4=0,a5=0,a6=0,a7=0;
        const float* xv = value + (size_t)bg * (Sn * DMn) + tid;
#pragma unroll 8
        for (int k = 0; k < 1024; k++) {
            float x = xv[(size_t)k * DMn];
            a0 += wb[0 * 1024 + k] * x;
            a1 += wb[1 * 1024 + k] * x;
            a2 += wb[2 * 1024 + k] * x;
            a3 += wb[3 * 1024 + k] * x;
            a4 += wb[4 * 1024 + k] * x;
            a5 += wb[5 * 1024 + k] * x;
            a6 += wb[6 * 1024 + k] * x;
            a7 += wb[7 * 1024 + k] * x;
        }
        ts[0 * 512 + tid] = a0; ts[1 * 512 + tid] = a1;
        ts[2 * 512 + tid] = a2; ts[3 * 512 + tid] = a3;
        ts[4 * 512 + tid] = a4; ts[5 * 512 + tid] = a5;
        ts[6 * 512 + tid] = a6; ts[7 * 512 + tid] = a7;
    }
    __syncthreads();

    {
        int h = tid >> 6, d = tid & 63;
        const float* wr = Wv + (size_t)tid * DMn;   // row h*64+d == tid
        const float* th = ts + h * 512;
        float o0=0,o1=0,o2=0,o3=0;
#pragma unroll 4
        for (int c2 = 0; c2 < 512; c2 += 4) {
            o0 += th[c2 + 0] * wr[c2 + 0];
            o1 += th[c2 + 1] * wr[c2 + 1];
            o2 += th[c2 + 2] * wr[c2 + 2];
            o3 += th[c2 + 3] * wr[c2 + 3];
        }
        fs[d * 8 + h] = bv[tid] + o0 + o1 + o2 + o3;
    }
    __syncthreads();

    if (write_y) {
        const float* wr = Wo + (size_t)tid * DMn;
        float o0=0,o1=0,o2=0,o3=0;
#pragma unroll 4
        for (int j = 0; j < 512; j += 4) {
            o0 += fs[j + 0] * wr[j + 0];
            o1 += fs[j + 1] * wr[j + 1];
            o2 += fs[j + 2] * wr[j + 2];
            o3 += fs[j + 3] * wr[j + 3];
        }
        out[bg * DMn + tid] = bo[tid] + o0 + o1 + o2 + o3;
    }
}

// ---------------------------------------------------------------------------
extern "C" void kernel_launch(void* const* d_in, const int* in_sizes, int n_in,
                              void* d_out, int out_size)
{
    if (n_in < 11) return;
    const float* query = (const float*)d_in[0];
    const float* key   = (const float*)d_in[1];
    const float* value = (const float*)d_in[2];
    const float* Wq = (const float*)d_in[3];
    const float* bq = (const float*)d_in[4];
    const float* Wk = (const float*)d_in[5];
    const float* bk = (const float*)d_in[6];
    const float* Wv = (const float*)d_in[7];
    const float* bv = (const float*)d_in[8];
    const float* Wo = (const float*)d_in[9];
    const float* bo = (const float*)d_in[10];
    float* out = (float*)d_out;

    const int write_p = (out_size >= P_ELEMS) ? 1 : 0;
    const int p_base  = (out_size > P_ELEMS) ? Y_ELEMS : 0;
    const int write_y = (out_size == Y_ELEMS || out_size == Y_ELEMS + P_ELEMS) ? 1 : 0;

    cudaFuncSetAttribute((const void*)attn_kernel,
                         cudaFuncAttributeMaxDynamicSharedMemorySize, ATTN_SMEM);
    cudaFuncSetAttribute((const void*)finalize_kernel,
                         cudaFuncAttributeMaxDynamicSharedMemorySize, F_SMEM);

    zero_wbar_kernel<<<192, 256>>>();
    proj_kernel<<<dim3(192, 4, 2), 256>>>(query, key, Wq, bq, Wk, bk);
    attn_kernel<<<dim3(32, 192), 256, ATTN_SMEM>>>(out, p_base, write_p);
    finalize_kernel<<<BG, 512, F_SMEM>>>(value, Wv, bv, Wo, bo, out, write_y);
}

// round 2
// speedup vs baseline: 1.4635x; 1.4635x over previous
#include <cuda_runtime.h>
#include <cuda_bf16.h>
#include <stdint.h>

// Problem constants
static constexpr int Bn = 4, Gn = 6, Hn = 8, Sn = 1024, DKn = 64, DMn = 512;
static constexpr int BG   = Bn * Gn;        // 24
static constexpr int BGH  = BG * Hn;        // 192
static constexpr int MROWS = BG * Sn;       // 24576
static constexpr int P_ELEMS = 201326592;   // 192*1024*1024
static constexpr int Y_ELEMS = BG * DMn;    // 12288

// Scratch (__device__ globals: allocation-free)
__device__ __align__(16) __nv_bfloat16 g_q[(size_t)MROWS * DMn];
__device__ __align__(16) __nv_bfloat16 g_k[(size_t)MROWS * DMn];
__device__ __align__(16) float g_wbar[BGH * Sn];
__device__ __align__(16) float g_t[BG * Hn * DMn];   // 24*8*512 partial t accum

__device__ __forceinline__ void mma16816(float c[4], const uint32_t a[4], const uint32_t b[2]) {
    asm volatile(
        "mma.sync.aligned.m16n8k16.row.col.f32.bf16.bf16.f32 "
        "{%0,%1,%2,%3},{%4,%5,%6,%7},{%8,%9},{%0,%1,%2,%3};\n"
        : "+f"(c[0]), "+f"(c[1]), "+f"(c[2]), "+f"(c[3])
        : "r"(a[0]), "r"(a[1]), "r"(a[2]), "r"(a[3]), "r"(b[0]), "r"(b[1]));
}

// ---------------------------------------------------------------------------
// Zero wbar (192*1024 floats) and g_t (24*4096 floats). grid 288 x 256thr x 4f
__global__ void zero_kernel() {
    int i = blockIdx.x * 1024 + threadIdx.x * 4;
    float4 z = make_float4(0.f, 0.f, 0.f, 0.f);
    if (i < BGH * Sn) *(float4*)&g_wbar[i] = z;
    else              *(float4*)&g_t[i - BGH * Sn] = z;
}

// ---------------------------------------------------------------------------
// Projection: y = x @ W^T + b, output bf16 in (bg, h, s, d) layout.
// Grid: (192 m-tiles, 4 n-tiles, 2 {q,k}), 256 threads.
__global__ __launch_bounds__(256) void proj_kernel(
    const float* __restrict__ xq, const float* __restrict__ xk,
    const float* __restrict__ Wq, const float* __restrict__ bq,
    const float* __restrict__ Wk, const float* __restrict__ bk)
{
    const int which = blockIdx.z;
    const float* __restrict__ X  = which ? xk : xq;
    const float* __restrict__ W  = which ? Wk : Wq;
    const float* __restrict__ Bi = which ? bk : bq;
    __nv_bfloat16* O = which ? g_k : g_q;

    const int m0 = blockIdx.x * 128;
    const int n0 = blockIdx.y * 128;
    const int tid = threadIdx.x;
    const int w = tid >> 5, lane = tid & 31;
    const int gq = lane >> 2, tq = lane & 3;
    const int wm = w >> 1, wn = w & 1;   // 4x2 warp grid -> warp tile 32(m) x 64(n)

    __shared__ __nv_bfloat16 As[128 * 40];
    __shared__ __nv_bfloat16 Bs[128 * 40];

    float acc[2][8][4];
#pragma unroll
    for (int mi = 0; mi < 2; mi++)
#pragma unroll
        for (int ni = 0; ni < 8; ni++)
#pragma unroll
            for (int x = 0; x < 4; x++) acc[mi][ni][x] = 0.f;

    float4 ra[4], rb[4];
#pragma unroll
    for (int j = 0; j < 4; j++) {
        int i = tid + 256 * j;
        int r = i >> 3, c4 = (i & 7) * 4;
        ra[j] = *(const float4*)&X[(size_t)(m0 + r) * DMn + c4];
        rb[j] = *(const float4*)&W[(size_t)(n0 + r) * DMn + c4];
    }

    for (int kc = 0; kc < 16; kc++) {
        __syncthreads();
#pragma unroll
        for (int j = 0; j < 4; j++) {
            int i = tid + 256 * j;
            int r = i >> 3, c4 = (i & 7) * 4;
            __nv_bfloat162 lo = __floats2bfloat162_rn(ra[j].x, ra[j].y);
            __nv_bfloat162 hi = __floats2bfloat162_rn(ra[j].z, ra[j].w);
            *(__nv_bfloat162*)&As[r * 40 + c4]     = lo;
            *(__nv_bfloat162*)&As[r * 40 + c4 + 2] = hi;
            lo = __floats2bfloat162_rn(rb[j].x, rb[j].y);
            hi = __floats2bfloat162_rn(rb[j].z, rb[j].w);
            *(__nv_bfloat162*)&Bs[r * 40 + c4]     = lo;
            *(__nv_bfloat162*)&Bs[r * 40 + c4 + 2] = hi;
        }
        __syncthreads();
        if (kc < 15) {
            int kk = (kc + 1) * 32;
#pragma unroll
            for (int j = 0; j < 4; j++) {
                int i = tid + 256 * j;
                int r = i >> 3, c4 = (i & 7) * 4;
                ra[j] = *(const float4*)&X[(size_t)(m0 + r) * DMn + kk + c4];
                rb[j] = *(const float4*)&W[(size_t)(n0 + r) * DMn + kk + c4];
            }
        }
#pragma unroll
        for (int ks = 0; ks < 32; ks += 16) {
            uint32_t af[2][4];
#pragma unroll
            for (int mi = 0; mi < 2; mi++) {
                int ar = wm * 32 + mi * 16;
                af[mi][0] = *(const uint32_t*)&As[(ar + gq) * 40 + ks + 2 * tq];
                af[mi][1] = *(const uint32_t*)&As[(ar + gq + 8) * 40 + ks + 2 * tq];
                af[mi][2] = *(const uint32_t*)&As[(ar + gq) * 40 + ks + 2 * tq + 8];
                af[mi][3] = *(const uint32_t*)&As[(ar + gq + 8) * 40 + ks + 2 * tq + 8];
            }
#pragma unroll
            for (int ni = 0; ni < 8; ni++) {
                int br = wn * 64 + ni * 8 + gq;
                uint32_t bf[2];
                bf[0] = *(const uint32_t*)&Bs[br * 40 + ks + 2 * tq];
                bf[1] = *(const uint32_t*)&Bs[br * 40 + ks + 2 * tq + 8];
#pragma unroll
                for (int mi = 0; mi < 2; mi++) mma16816(acc[mi][ni], af[mi], bf);
            }
        }
    }

    // Epilogue: +bias, convert bf16, write to (bg,h,s,d) layout
#pragma unroll
    for (int ni = 0; ni < 8; ni++) {
        int cc = n0 + wn * 64 + ni * 8 + 2 * tq;
        float b0v = Bi[cc], b1v = Bi[cc + 1];
        int h = cc >> 6, d = cc & 63;
#pragma unroll
        for (int mi = 0; mi < 2; mi++) {
            int rbase = m0 + wm * 32 + mi * 16 + gq;
#pragma unroll
            for (int rr = 0; rr < 2; rr++) {
                int r = rbase + rr * 8;
                int bg = r >> 10, s = r & 1023;
                size_t off = ((size_t)(bg * Hn + h) * Sn + s) * DKn + d;
                float v0 = acc[mi][ni][rr * 2 + 0] + b0v;
                float v1 = acc[mi][ni][rr * 2 + 1] + b1v;
                *(__nv_bfloat162*)&O[off] = __floats2bfloat162_rn(v0, v1);
            }
        }
    }
}

// ---------------------------------------------------------------------------
// Attention: per CTA = (32 q-rows) x (full 1024 k) of one (b,g,h).
// Single pass: bf16 MMA scores -> exp into smem -> rowsum -> normalized write
// + column-sum atomics into g_wbar.
static constexpr int ESTR = 1028;  // padded fp32 row stride for e-tile
static constexpr int ATTN_SMEM = 32 * ESTR * 4      // e tile      131584
                               + 32 * 72 * 2        // q tile        4608
                               + 128 * 72 * 2       // k chunk      18432
                               + 32 * 4;            // rowsum         128

__global__ __launch_bounds__(256) void attn_kernel(float* __restrict__ out, int p_base, int write_p)
{
    extern __shared__ char smbuf[];
    float*        es  = (float*)smbuf;
    __nv_bfloat16* qs  = (__nv_bfloat16*)(smbuf + 32 * ESTR * 4);
    __nv_bfloat16* ksm = (__nv_bfloat16*)(smbuf + 32 * ESTR * 4 + 32 * 72 * 2);
    float*        rsum = (float*)(smbuf + 32 * ESTR * 4 + 32 * 72 * 2 + 128 * 72 * 2);

    const int qt = blockIdx.x, bgh = blockIdx.y;
    const int tid = threadIdx.x;
    const int w = tid >> 5, lane = tid & 31;
    const int gq = lane >> 2, tq = lane & 3;
    const int wm = w & 1, wn = w >> 1;   // 2(m) x 4(n) warp grid over 32 x 128

    const __nv_bfloat16* qbase = g_q + (size_t)bgh * (Sn * DKn) + (size_t)qt * 32 * DKn;
    const __nv_bfloat16* kbase = g_k + (size_t)bgh * (Sn * DKn);

    // load q tile (32x64 bf16) into smem, padded stride 72
    {
        int r = tid >> 3, part = tid & 7;
        *(uint4*)&qs[r * 72 + part * 8] = *(const uint4*)&qbase[r * DKn + part * 8];
    }
    if (tid < 32) rsum[tid] = 0.f;

    float rs0 = 0.f, rs1 = 0.f;

    uint4 pre[4];
#pragma unroll
    for (int j = 0; j < 4; j++) {
        int i = tid + 256 * j;
        int r = i >> 3, part = i & 7;
        pre[j] = *(const uint4*)&kbase[(size_t)r * DKn + part * 8];
    }

    const float SCL = 1.0f / 1200.0f;  // 1/(sqrt(64)*150)

    for (int c = 0; c < 8; c++) {
        __syncthreads();
#pragma unroll
        for (int j = 0; j < 4; j++) {
            int i = tid + 256 * j;
            int r = i >> 3, part = i & 7;
            *(uint4*)&ksm[r * 72 + part * 8] = pre[j];
        }
        __syncthreads();
        if (c < 7) {
#pragma unroll
            for (int j = 0; j < 4; j++) {
                int i = tid + 256 * j;
                int r = i >> 3, part = i & 7;
                pre[j] = *(const uint4*)&kbase[(size_t)((c + 1) * 128 + r) * DKn + part * 8];
            }
        }

        float acc[4][4];
#pragma unroll
        for (int ni = 0; ni < 4; ni++)
#pragma unroll
            for (int x = 0; x < 4; x++) acc[ni][x] = 0.f;

#pragma unroll
        for (int ks = 0; ks < 64; ks += 16) {
            uint32_t af[4];
            int ar = wm * 16;
            af[0] = *(const uint32_t*)&qs[(ar + gq) * 72 + ks + 2 * tq];
            af[1] = *(const uint32_t*)&qs[(ar + gq + 8) * 72 + ks + 2 * tq];
            af[2] = *(const uint32_t*)&qs[(ar + gq) * 72 + ks + 2 * tq + 8];
            af[3] = *(const uint32_t*)&qs[(ar + gq + 8) * 72 + ks + 2 * tq + 8];
#pragma unroll
            for (int ni = 0; ni < 4; ni++) {
                int br = wn * 32 + ni * 8 + gq;
                uint32_t bf[2];
                bf[0] = *(const uint32_t*)&ksm[br * 72 + ks + 2 * tq];
                bf[1] = *(const uint32_t*)&ksm[br * 72 + ks + 2 * tq + 8];
                mma16816(acc[ni], af, bf);
            }
        }

        int r0 = wm * 16 + gq;
#pragma unroll
        for (int ni = 0; ni < 4; ni++) {
            int cc = c * 128 + wn * 32 + ni * 8 + 2 * tq;
            float e00 = __expf(acc[ni][0] * SCL);
            float e01 = __expf(acc[ni][1] * SCL);
            float e10 = __expf(acc[ni][2] * SCL);
            float e11 = __expf(acc[ni][3] * SCL);
            *(float2*)&es[r0 * ESTR + cc]       = make_float2(e00, e01);
            *(float2*)&es[(r0 + 8) * ESTR + cc] = make_float2(e10, e11);
            rs0 += e00 + e01;
            rs1 += e10 + e11;
        }
    }

    // reduce row partials within lane quads, then shared atomics
    rs0 += __shfl_xor_sync(0xffffffffu, rs0, 1);
    rs0 += __shfl_xor_sync(0xffffffffu, rs0, 2);
    rs1 += __shfl_xor_sync(0xffffffffu, rs1, 1);
    rs1 += __shfl_xor_sync(0xffffffffu, rs1, 2);
    if (tq == 0) {
        atomicAdd(&rsum[wm * 16 + gq], rs0);
        atomicAdd(&rsum[wm * 16 + 8 + gq], rs1);
    }
    __syncthreads();
    if (tid < 32) rsum[tid] = 1.0f / rsum[tid];   // invert once
    __syncthreads();

    // normalize + write p + accumulate column sums (thread owns cols tid*4..+3)
    float cs0 = 0.f, cs1 = 0.f, cs2 = 0.f, cs3 = 0.f;
    float* pout = out + p_base + (size_t)bgh * ((size_t)Sn * Sn) + (size_t)(qt * 32) * Sn;
#pragma unroll 4
    for (int r = 0; r < 32; r++) {
        float inv = rsum[r];
        float4 v = *(const float4*)&es[r * ESTR + tid * 4];
        v.x *= inv; v.y *= inv; v.z *= inv; v.w *= inv;
        cs0 += v.x; cs1 += v.y; cs2 += v.z; cs3 += v.w;
        if (write_p) *(float4*)&pout[(size_t)r * Sn + tid * 4] = v;
    }
    atomicAdd(&g_wbar[bgh * Sn + tid * 4 + 0], cs0);
    atomicAdd(&g_wbar[bgh * Sn + tid * 4 + 1], cs1);
    atomicAdd(&g_wbar[bgh * Sn + tid * 4 + 2], cs2);
    atomicAdd(&g_wbar[bgh * Sn + tid * 4 + 3], cs3);
}

// ---------------------------------------------------------------------------
// t = (wbar/1024) @ Xv, parallelized over (bg, 16 S-chunks of 64).
// Each CTA: 256 threads; thread owns columns tid and tid+256; 8 head accums each.
__global__ __launch_bounds__(256) void t_kernel(const float* __restrict__ value)
{
    __shared__ float wb[8][64];
    const int bg = blockIdx.x, kc = blockIdx.y;
    const int tid = threadIdx.x;

    for (int j = tid; j < 512; j += 256) {
        int h = j >> 6, k = j & 63;
        wb[h][k] = g_wbar[(bg * 8 + h) * Sn + kc * 64 + k] * (1.0f / 1024.0f);
    }
    __syncthreads();

    float a[8][2];
#pragma unroll
    for (int h = 0; h < 8; h++) { a[h][0] = 0.f; a[h][1] = 0.f; }

    const float* __restrict__ xv = value + (size_t)bg * (Sn * DMn) + (size_t)(kc * 64) * DMn;
#pragma unroll 4
    for (int k = 0; k < 64; k++) {
        float x0 = xv[k * DMn + tid];
        float x1 = xv[k * DMn + tid + 256];
#pragma unroll
        for (int h = 0; h < 8; h++) {
            a[h][0] += wb[h][k] * x0;
            a[h][1] += wb[h][k] * x1;
        }
    }
#pragma unroll
    for (int h = 0; h < 8; h++) {
        atomicAdd(&g_t[(bg * 8 + h) * DMn + tid],       a[h][0]);
        atomicAdd(&g_t[(bg * 8 + h) * DMn + tid + 256], a[h][1]);
    }
}

// ---------------------------------------------------------------------------
// finalize2: out_hd = t_h . Wv[h*64+d] + bv ; f[d*8+h] = out_hd ;
// y = f @ Wo^T + bo.  One CTA per (b,g), 512 threads, row-contiguous W loads.
__global__ __launch_bounds__(512) void finalize2_kernel(
    const float* __restrict__ Wv, const float* __restrict__ bv,
    const float* __restrict__ Wo, const float* __restrict__ bo,
    float* __restrict__ out, int write_y)
{
    __shared__ float ts[8 * 512];
    __shared__ float fs[512];
    const int bg = blockIdx.x, tid = threadIdx.x;

#pragma unroll
    for (int j = 0; j < 8; j++) ts[j * 512 + tid] = g_t[bg * 4096 + j * 512 + tid];
    __syncthreads();

    {
        int h = tid >> 6, d = tid & 63;
        const float4* __restrict__ wr = (const float4*)(Wv + (size_t)tid * DMn);
        const float* th = ts + h * 512;
        float o0 = 0, o1 = 0, o2 = 0, o3 = 0;
#pragma unroll 8
        for (int c = 0; c < 128; c++) {
            float4 w4 = wr[c];
            o0 += th[4 * c + 0] * w4.x;
            o1 += th[4 * c + 1] * w4.y;
            o2 += th[4 * c + 2] * w4.z;
            o3 += th[4 * c + 3] * w4.w;
        }
        fs[d * 8 + h] = bv[tid] + ((o0 + o1) + (o2 + o3));
    }
    __syncthreads();

    if (write_y) {
        const float4* __restrict__ wr = (const float4*)(Wo + (size_t)tid * DMn);
        float o0 = 0, o1 = 0, o2 = 0, o3 = 0;
#pragma unroll 8
        for (int c = 0; c < 128; c++) {
            float4 w4 = wr[c];
            o0 += fs[4 * c + 0] * w4.x;
            o1 += fs[4 * c + 1] * w4.y;
            o2 += fs[4 * c + 2] * w4.z;
            o3 += fs[4 * c + 3] * w4.w;
        }
        out[bg * DMn + tid] = bo[tid] + ((o0 + o1) + (o2 + o3));
    }
}

// ---------------------------------------------------------------------------
extern "C" void kernel_launch(void* const* d_in, const int* in_sizes, int n_in,
                              void* d_out, int out_size)
{
    if (n_in < 11) return;
    const float* query = (const float*)d_in[0];
    const float* key   = (const float*)d_in[1];
    const float* value = (const float*)d_in[2];
    const float* Wq = (const float*)d_in[3];
    const float* bq = (const float*)d_in[4];
    const float* Wk = (const float*)d_in[5];
    const float* bk = (const float*)d_in[6];
    const float* Wv = (const float*)d_in[7];
    const float* bv = (const float*)d_in[8];
    const float* Wo = (const float*)d_in[9];
    const float* bo = (const float*)d_in[10];
    float* out = (float*)d_out;

    const int write_p = (out_size >= P_ELEMS) ? 1 : 0;
    const int p_base  = (out_size > P_ELEMS) ? Y_ELEMS : 0;
    const int write_y = (out_size == Y_ELEMS || out_size == Y_ELEMS + P_ELEMS) ? 1 : 0;

    cudaFuncSetAttribute((const void*)attn_kernel,
                         cudaFuncAttributeMaxDynamicSharedMemorySize, ATTN_SMEM);

    zero_kernel<<<288, 256>>>();
    proj_kernel<<<dim3(192, 4, 2), 256>>>(query, key, Wq, bq, Wk, bk);
    attn_kernel<<<dim3(32, 192), 256, ATTN_SMEM>>>(out, p_base, write_p);
    t_kernel<<<dim3(BG, 16), 256>>>(value);
    finalize2_kernel<<<BG, 512>>>(Wv, bv, Wo, bo, out, write_y);
}